// round 10
// baseline (speedup 1.0000x reference)
#include <cuda_runtime.h>

// NeRF volume rendering compositing — round 10: trim sigma/dists over-read.
// Inputs (metadata order):
//   d_in[0]: sigma  [B, S]    float32   (B=65536, S=512)
//   d_in[1]: dists  [B, S]    float32
//   d_in[2]: rgb    [B, S, 3] float32
//   d_in[3]: bg_col [3]       float32
// Output: rgb_map [B, 3] float32
//
//   x = sigma*dists*25; alpha = 1-exp(-x); T = excl cumprod(exp(-x)+1e-10)
//   w = alpha*T; out_c = sum w*clip(rgb,0,1) + (1-sum w)*bg_c
//
// Two rays per warp (16-lane segments), float4 loads, default-cached (L2
// retention across graph replays — R8 win). Round 0 covers only samples
// 0..47: lanes 0..11 load sigma/dists, lanes 12..15 contribute neutral
// p=1 to the scan. At tau=3e-4 only ~0.5% of segments survive past sample
// 48; those continue in 64-sample tail rounds (samples 48+). rgb loads are
// scan-predicated per lane as before (~9 active lanes/ray). Truncation
// error telescopes to < tau abs; measured coefficient 0.64*tau ->
// rel_err ~1.9e-4 vs the 1e-3 gate (5x margin).
// Expected traffic ~53.5 MB (was ~65 MB).

#define DIST_SCALE 25.0f
#define T_THRESH   3e-4f
#define FULLMASK   0xffffffffu
#define SEGW       16
#define R0LANES    12          // round-0 sigma/dists lanes (48 samples)

__device__ __forceinline__ float clip01(float v) {
    return fminf(fmaxf(v, 0.0f), 1.0f);
}

struct Factors { float w0, w1, w2, w3, p; };

__device__ __forceinline__ Factors factors(const float4& sg, const float4& dt) {
    const float f0 = __expf(-DIST_SCALE * sg.x * dt.x);
    const float f1 = __expf(-DIST_SCALE * sg.y * dt.y);
    const float f2 = __expf(-DIST_SCALE * sg.z * dt.z);
    const float f3 = __expf(-DIST_SCALE * sg.w * dt.w);
    const float g0 = f0 + 1e-10f;
    const float g1 = f1 + 1e-10f;
    const float g2 = f2 + 1e-10f;
    const float g3 = f3 + 1e-10f;
    Factors r;
    r.w0 = (1.0f - f0);
    float t = g0;
    r.w1 = (1.0f - f1) * t;  t *= g1;
    r.w2 = (1.0f - f2) * t;  t *= g2;
    r.w3 = (1.0f - f3) * t;
    r.p  = t * g3;
    return r;
}

// Width-16 segment scan: exclusive prefix product + segment total.
__device__ __forceinline__ void seg_scan(float p, int slane, float& excl, float& total) {
    float incl = p;
    #pragma unroll
    for (int off = 1; off < SEGW; off <<= 1) {
        const float v = __shfl_up_sync(FULLMASK, incl, off, SEGW);
        if (slane >= off) incl *= v;
    }
    excl = __shfl_up_sync(FULLMASK, incl, 1, SEGW);
    if (slane == 0) excl = 1.0f;
    total = __shfl_sync(FULLMASK, incl, SEGW - 1, SEGW);
}

__global__ __launch_bounds__(256, 8)
void nerf_composite_kernel(const float4* __restrict__ sigma4,
                           const float4* __restrict__ dists4,
                           const float4* __restrict__ rgb4,
                           const float*  __restrict__ bg,
                           float*        __restrict__ out,
                           int B)
{
    const int warp  = (int)((blockIdx.x * (unsigned)blockDim.x + threadIdx.x) >> 5);
    const int lane  = threadIdx.x & 31;
    const int slane = lane & (SEGW - 1);        // lane within 16-lane segment
    const int ray   = warp * 2 + (lane >> 4);   // one ray per half-warp
    if (ray >= B) return;

    float accW = 0.0f, accR = 0.0f, accG = 0.0f, accB = 0.0f;

    // ---- Round 0: samples 0..47 (lanes 0..11), scan over 16 lanes ----
    const bool act0 = (slane < R0LANES);
    float p0 = 1.0f;
    Factors fc;
    fc.w0 = fc.w1 = fc.w2 = fc.w3 = 0.0f;
    if (act0) {
        const int idx = ray * 128 + slane;           // float4 idx: samples 4*slane..
        const float4 sg = sigma4[idx];
        const float4 dt = dists4[idx];
        fc = factors(sg, dt);
        p0 = fc.p;
    }

    float excl, total;
    seg_scan(p0, slane, excl, total);
    const float Tl0 = excl;

    if (act0 && (Tl0 >= T_THRESH)) {
        const int ridx = ray * 384 + slane * 3;
        const float4 q0 = rgb4[ridx + 0];
        const float4 q1 = rgb4[ridx + 1];
        const float4 q2 = rgb4[ridx + 2];
        const float w0 = fc.w0 * Tl0, w1 = fc.w1 * Tl0,
                    w2 = fc.w2 * Tl0, w3 = fc.w3 * Tl0;
        accR += w0 * clip01(q0.x) + w1 * clip01(q0.w)
              + w2 * clip01(q1.z) + w3 * clip01(q2.y);
        accG += w0 * clip01(q0.y) + w1 * clip01(q1.x)
              + w2 * clip01(q1.w) + w3 * clip01(q2.z);
        accB += w0 * clip01(q0.z) + w1 * clip01(q1.y)
              + w2 * clip01(q2.x) + w3 * clip01(q2.w);
        accW += w0 + w1 + w2 + w3;
    }

    float T_run = total;

    // ---- Tail rounds: samples 48.. in 64-sample chunks (~0.5% of segments) ----
    if (!__all_sync(FULLMASK, T_run < T_THRESH)) {
        #pragma unroll 1
        for (int k = 0; k < 8; ++k) {
            // float4 index within the ray: 12 + k*16 + slane  (must be < 128)
            const int fidx  = R0LANES + k * 16 + slane;
            const bool valid = (fidx < 128);

            float pk = 1.0f;
            Factors fck;
            fck.w0 = fck.w1 = fck.w2 = fck.w3 = 0.0f;
            if (valid) {
                const int idx = ray * 128 + fidx;
                const float4 sg = sigma4[idx];
                const float4 dt = dists4[idx];
                fck = factors(sg, dt);
                pk = fck.p;
            }

            float exclk, totalk;
            seg_scan(pk, slane, exclk, totalk);
            const float Tl = T_run * exclk;

            if (valid && (Tl >= T_THRESH)) {
                const int ridx = ray * 384 + fidx * 3;
                const float4 a0 = rgb4[ridx + 0];
                const float4 a1 = rgb4[ridx + 1];
                const float4 a2 = rgb4[ridx + 2];
                const float w0 = fck.w0 * Tl, w1 = fck.w1 * Tl,
                            w2 = fck.w2 * Tl, w3 = fck.w3 * Tl;
                accR += w0 * clip01(a0.x) + w1 * clip01(a0.w)
                      + w2 * clip01(a1.z) + w3 * clip01(a2.y);
                accG += w0 * clip01(a0.y) + w1 * clip01(a1.x)
                      + w2 * clip01(a1.w) + w3 * clip01(a2.z);
                accB += w0 * clip01(a0.z) + w1 * clip01(a1.y)
                      + w2 * clip01(a2.x) + w3 * clip01(a2.w);
                accW += w0 + w1 + w2 + w3;
            }

            T_run *= totalk;
            if (__all_sync(FULLMASK, T_run < T_THRESH)) break;
            if (R0LANES + (k + 1) * 16 >= 128) break;   // all samples consumed
        }
    }

    // ---- Segment reduction + output ----
    #pragma unroll
    for (int off = SEGW / 2; off >= 1; off >>= 1) {
        accW += __shfl_down_sync(FULLMASK, accW, off, SEGW);
        accR += __shfl_down_sync(FULLMASK, accR, off, SEGW);
        accG += __shfl_down_sync(FULLMASK, accG, off, SEGW);
        accB += __shfl_down_sync(FULLMASK, accB, off, SEGW);
    }

    if (slane == 0) {
        const float rem = 1.0f - accW;
        out[ray * 3 + 0] = accR + rem * __ldg(&bg[0]);
        out[ray * 3 + 1] = accG + rem * __ldg(&bg[1]);
        out[ray * 3 + 2] = accB + rem * __ldg(&bg[2]);
    }
}

extern "C" void kernel_launch(void* const* d_in, const int* in_sizes, int n_in,
                              void* d_out, int out_size)
{
    const float4* sigma4 = (const float4*)d_in[0];
    const float4* dists4 = (const float4*)d_in[1];
    const float4* rgb4   = (const float4*)d_in[2];
    const float*  bg     = (const float*) d_in[3];
    float*        out    = (float*)d_out;

    const int B = in_sizes[0] / 512;           // 65536 rays
    const int threads = 256;                    // 8 warps/block -> 16 rays/block
    const int blocks  = (B + 15) / 16;

    nerf_composite_kernel<<<blocks, threads>>>(sigma4, dists4, rgb4, bg, out, B);
}